// round 2
// baseline (speedup 1.0000x reference)
#include <cuda_runtime.h>

#define N 2048
#define BATCH 16
#define THREADS 256
#define PER 8   // N / THREADS

__device__ float g_bsum[BATCH * N];

// One warp per output j: short accumulation chains + tree reduce for accuracy.
__global__ void __launch_bounds__(THREADS) bsum_kernel(const float* __restrict__ scores) {
    __shared__ float s[N];
    int b = blockIdx.y;
    const float* sp = scores + (size_t)b * N;
    for (int j = threadIdx.x; j < N; j += blockDim.x) s[j] = sp[j];
    __syncthreads();

    int warp = threadIdx.x >> 5;
    int lane = threadIdx.x & 31;
    int j = blockIdx.x * 8 + warp;          // 8 warps per block, N/8 blocks in x
    float sj = s[j];
    float acc = 0.0f;
    #pragma unroll 8
    for (int i = lane; i < N; i += 32)
        acc += fabsf(sj - s[i]);
    #pragma unroll
    for (int o = 16; o > 0; o >>= 1)
        acc += __shfl_xor_sync(0xFFFFFFFFu, acc, o);
    if (lane == 0) g_bsum[(size_t)b * N + j] = acc;
}

__device__ __forceinline__ float block_reduce_max(float v, float* sh) {
    #pragma unroll
    for (int o = 16; o > 0; o >>= 1)
        v = fmaxf(v, __shfl_xor_sync(0xFFFFFFFFu, v, o));
    int wid = threadIdx.x >> 5;
    int lane = threadIdx.x & 31;
    if (lane == 0) sh[wid] = v;
    __syncthreads();
    if (wid == 0) {
        v = (lane < (THREADS / 32)) ? sh[lane] : -INFINITY;
        #pragma unroll
        for (int o = 4; o > 0; o >>= 1)
            v = fmaxf(v, __shfl_xor_sync(0xFFFFFFFFu, v, o));
        if (lane == 0) sh[0] = v;
    }
    __syncthreads();
    return sh[0];
}

__device__ __forceinline__ float block_reduce_sum(float v, float* sh) {
    #pragma unroll
    for (int o = 16; o > 0; o >>= 1)
        v += __shfl_xor_sync(0xFFFFFFFFu, v, o);
    int wid = threadIdx.x >> 5;
    int lane = threadIdx.x & 31;
    if (lane == 0) sh[wid] = v;
    __syncthreads();
    if (wid == 0) {
        v = (lane < (THREADS / 32)) ? sh[lane] : 0.0f;
        #pragma unroll
        for (int o = 4; o > 0; o >>= 1)
            v += __shfl_xor_sync(0xFFFFFFFFu, v, o);
        if (lane == 0) sh[0] = v;
    }
    __syncthreads();
    return sh[0];
}

__global__ void __launch_bounds__(THREADS) softmax_kernel(
    const float* __restrict__ scores, float* __restrict__ out)
{
    int i = blockIdx.x;   // output row within batch
    int b = blockIdx.y;   // batch
    float a = (float)(N - 1 - 2 * i);   // scaling[i] = 2047 - 2i

    const float4* s4  = (const float4*)(scores + (size_t)b * N);
    const float4* bs4 = (const float4*)(g_bsum + (size_t)b * N);
    float4* o4 = (float4*)(out + ((size_t)b * N + i) * N);

    __shared__ float sh[THREADS / 32];

    int t = threadIdx.x;
    float vals[PER];
    float m = -INFINITY;

    // Match reference rounding: C = s*a (round), P = C - Bsum (round). NO fma.
    #pragma unroll
    for (int c = 0; c < 2; c++) {
        int idx = t + c * THREADS;
        float4 sv = s4[idx];
        float4 bv = bs4[idx];
        float v0 = __fsub_rn(__fmul_rn(a, sv.x), bv.x);
        float v1 = __fsub_rn(__fmul_rn(a, sv.y), bv.y);
        float v2 = __fsub_rn(__fmul_rn(a, sv.z), bv.z);
        float v3 = __fsub_rn(__fmul_rn(a, sv.w), bv.w);
        vals[c * 4 + 0] = v0; vals[c * 4 + 1] = v1;
        vals[c * 4 + 2] = v2; vals[c * 4 + 3] = v3;
        m = fmaxf(m, fmaxf(fmaxf(v0, v1), fmaxf(v2, v3)));
    }

    m = block_reduce_max(m, sh);

    float lsum = 0.0f;
    #pragma unroll
    for (int k = 0; k < PER; k++) {
        float e = __expf(__fsub_rn(vals[k], m));
        vals[k] = e;
        lsum += e;
    }

    __syncthreads();   // sh reuse hazard between reductions
    float total = block_reduce_sum(lsum, sh);
    float inv = 1.0f / total;   // IEEE division, once per thread

    #pragma unroll
    for (int c = 0; c < 2; c++) {
        int idx = t + c * THREADS;
        float4 r;
        r.x = vals[c * 4 + 0] * inv;
        r.y = vals[c * 4 + 1] * inv;
        r.z = vals[c * 4 + 2] * inv;
        r.w = vals[c * 4 + 3] * inv;
        __stcs(&o4[idx], r);   // streaming store: evict-first, 256MB write-once
    }
}

extern "C" void kernel_launch(void* const* d_in, const int* in_sizes, int n_in,
                              void* d_out, int out_size) {
    const float* scores = (const float*)d_in[0];
    float* out = (float*)d_out;

    dim3 bgrid(N / 8, BATCH);
    bsum_kernel<<<bgrid, THREADS>>>(scores);
    dim3 grid(N, BATCH);
    softmax_kernel<<<grid, THREADS>>>(scores, out);
}